// round 2
// baseline (speedup 1.0000x reference)
#include <cuda_runtime.h>
#include <cuda_bf16.h>
#include <cstddef>

// Problem constants (fixed shapes for this dataset)
#define N_NODES   50000
#define N_GRAPHS  128
#define IN_C      128
#define HID_C     128
#define OUT_C     64

// ---------------- device scratch (no allocations allowed) ----------------
__device__ int   g_degi[N_NODES];
__device__ float g_dinv[N_NODES];
__device__ float g_g1  [(size_t)N_NODES * HID_C];   // dinv * (x @ W1)
__device__ float g_acc1[(size_t)N_NODES * HID_C];   // scatter accumulator layer 1
__device__ float g_g2  [(size_t)N_NODES * OUT_C];   // dinv * (t @ W2)
__device__ float g_acc2[(size_t)N_NODES * OUT_C];   // scatter accumulator layer 2
__device__ float g_gsum[N_GRAPHS * OUT_C];
__device__ float g_gcnt[N_GRAPHS];

// ---------------- degree / dinv ----------------
__global__ void deg_kernel(const int* __restrict__ dst, int E) {
    int e = blockIdx.x * blockDim.x + threadIdx.x;
    if (e < E) atomicAdd(&g_degi[dst[e]], 1);
}

__global__ void dinv_kernel(int N) {
    int i = blockIdx.x * blockDim.x + threadIdx.x;
    if (i < N) g_dinv[i] = rsqrtf((float)(1 + g_degi[i]));  // +1 self-loop
}

// ---------------- GEMM1: g1 = dinv ⊙ (X @ W1)  [M,128]x[128,128] ----------------
// BM=64, BN=128, BK=16, TM=4, TN=8, 256 threads.
__global__ void gemm1_kernel(const float* __restrict__ X,
                             const float* __restrict__ W,
                             int M) {
    __shared__ __align__(16) float xs[16][68];    // [k][m], padded
    __shared__ __align__(16) float ws[16][128];   // [k][n]

    const int tid = threadIdx.x;
    const int tn  = tid & 15;   // n-block: tn*8
    const int tm  = tid >> 4;   // m-block: tm*4
    const int row0 = blockIdx.x * 64;

    float acc[4][8];
#pragma unroll
    for (int m = 0; m < 4; m++)
#pragma unroll
        for (int n = 0; n < 8; n++) acc[m][n] = 0.f;

    const int lm = tid >> 2;          // 0..63 (row within tile for loads)
    const int lk = (tid & 3) * 4;     // k-quad for loads

    for (int k0 = 0; k0 < IN_C; k0 += 16) {
        // load X tile (transposed into xs)
        {
            int row = row0 + lm;
            float4 v = make_float4(0.f, 0.f, 0.f, 0.f);
            if (row < M)
                v = *(const float4*)(X + (size_t)row * IN_C + k0 + lk);
            xs[lk + 0][lm] = v.x;
            xs[lk + 1][lm] = v.y;
            xs[lk + 2][lm] = v.z;
            xs[lk + 3][lm] = v.w;
        }
        // load W tile: 16x128 = 512 float4, 2 per thread
#pragma unroll
        for (int i = 0; i < 2; i++) {
            int idx4 = tid + i * 256;      // 0..511
            int k  = idx4 >> 5;            // /32 float4 per row
            int n4 = idx4 & 31;
            *(float4*)(&ws[k][n4 * 4]) =
                *(const float4*)(W + (size_t)(k0 + k) * HID_C + n4 * 4);
        }
        __syncthreads();

#pragma unroll
        for (int k = 0; k < 16; k++) {
            float xr[4], wr[8];
#pragma unroll
            for (int m = 0; m < 4; m++) xr[m] = xs[k][tm * 4 + m];
#pragma unroll
            for (int n = 0; n < 8; n++) wr[n] = ws[k][tn * 8 + n];
#pragma unroll
            for (int m = 0; m < 4; m++)
#pragma unroll
                for (int n = 0; n < 8; n++) acc[m][n] += xr[m] * wr[n];
        }
        __syncthreads();
    }

#pragma unroll
    for (int m = 0; m < 4; m++) {
        int row = row0 + tm * 4 + m;
        if (row < M) {
            float d = g_dinv[row];
            float* out = g_g1 + (size_t)row * HID_C + tn * 8;
#pragma unroll
            for (int n = 0; n < 8; n++) out[n] = d * acc[m][n];
        }
    }
}

// ---------------- scatter layer 1: acc1[dst] += g1[src] (128 floats/edge) ----------------
__global__ void scatter1_kernel(const int* __restrict__ src,
                                const int* __restrict__ dst,
                                int E) {
    int warp = (blockIdx.x * blockDim.x + threadIdx.x) >> 5;
    int lane = threadIdx.x & 31;
    if (warp >= E) return;
    int s = src[warp];
    int d = dst[warp];
    float4 v = ((const float4*)(g_g1 + (size_t)s * HID_C))[lane];
    float* a = g_acc1 + (size_t)d * HID_C + lane * 4;
    atomicAdd(a + 0, v.x);
    atomicAdd(a + 1, v.y);
    atomicAdd(a + 2, v.z);
    atomicAdd(a + 3, v.w);
}

// ---------------- GEMM2 (fused): t = relu(dinv*(acc1+g1)+b1); g2 = dinv ⊙ (t @ W2) ----------------
// BM=64, BN=64, BK=16, TM=4, TN=4, 256 threads.
__global__ void gemm2_kernel(const float* __restrict__ W2,
                             const float* __restrict__ b1,
                             int M) {
    __shared__ __align__(16) float xs[16][68];   // [k][m]
    __shared__ __align__(16) float ws[16][64];   // [k][n]

    const int tid = threadIdx.x;
    const int tn  = tid & 15;   // n-block: tn*4
    const int tm  = tid >> 4;   // m-block: tm*4
    const int row0 = blockIdx.x * 64;

    float acc[4][4];
#pragma unroll
    for (int m = 0; m < 4; m++)
#pragma unroll
        for (int n = 0; n < 4; n++) acc[m][n] = 0.f;

    const int lm = tid >> 2;
    const int lk = (tid & 3) * 4;

    for (int k0 = 0; k0 < HID_C; k0 += 16) {
        // build input tile on the fly: relu(dinv*(acc1+g1)+b1)
        {
            int row = row0 + lm;
            float4 r = make_float4(0.f, 0.f, 0.f, 0.f);
            if (row < M) {
                float dv = g_dinv[row];
                float4 av = *(const float4*)(g_acc1 + (size_t)row * HID_C + k0 + lk);
                float4 gv = *(const float4*)(g_g1   + (size_t)row * HID_C + k0 + lk);
                float4 bv = *(const float4*)(b1 + k0 + lk);
                r.x = fmaxf(dv * (av.x + gv.x) + bv.x, 0.f);
                r.y = fmaxf(dv * (av.y + gv.y) + bv.y, 0.f);
                r.z = fmaxf(dv * (av.z + gv.z) + bv.z, 0.f);
                r.w = fmaxf(dv * (av.w + gv.w) + bv.w, 0.f);
            }
            xs[lk + 0][lm] = r.x;
            xs[lk + 1][lm] = r.y;
            xs[lk + 2][lm] = r.z;
            xs[lk + 3][lm] = r.w;
        }
        // load W2 tile: 16x64 = 256 float4, 1 per thread
        {
            int k  = tid >> 4;
            int n4 = tid & 15;
            *(float4*)(&ws[k][n4 * 4]) =
                *(const float4*)(W2 + (size_t)(k0 + k) * OUT_C + n4 * 4);
        }
        __syncthreads();

#pragma unroll
        for (int k = 0; k < 16; k++) {
            float xr[4], wr[4];
#pragma unroll
            for (int m = 0; m < 4; m++) xr[m] = xs[k][tm * 4 + m];
#pragma unroll
            for (int n = 0; n < 4; n++) wr[n] = ws[k][tn * 4 + n];
#pragma unroll
            for (int m = 0; m < 4; m++)
#pragma unroll
                for (int n = 0; n < 4; n++) acc[m][n] += xr[m] * wr[n];
        }
        __syncthreads();
    }

#pragma unroll
    for (int m = 0; m < 4; m++) {
        int row = row0 + tm * 4 + m;
        if (row < M) {
            float d = g_dinv[row];
            float* out = g_g2 + (size_t)row * OUT_C + tn * 4;
#pragma unroll
            for (int n = 0; n < 4; n++) out[n] = d * acc[m][n];
        }
    }
}

// ---------------- scatter layer 2: acc2[dst] += g2[src] (64 floats/edge, 16 lanes/edge) ----------------
__global__ void scatter2_kernel(const int* __restrict__ src,
                                const int* __restrict__ dst,
                                int E) {
    int t = blockIdx.x * blockDim.x + threadIdx.x;
    int e = t >> 4;
    int lane = t & 15;
    if (e >= E) return;
    int s = src[e];
    int d = dst[e];
    float4 v = ((const float4*)(g_g2 + (size_t)s * OUT_C))[lane];
    float* a = g_acc2 + (size_t)d * OUT_C + lane * 4;
    atomicAdd(a + 0, v.x);
    atomicAdd(a + 1, v.y);
    atomicAdd(a + 2, v.z);
    atomicAdd(a + 3, v.w);
}

// ---------------- pool: out2 = dinv*(acc2+g2)+b2; scatter to graph sums ----------------
__global__ void pool_kernel(const int* __restrict__ batch,
                            const float* __restrict__ b2,
                            int N) {
    int t = blockIdx.x * blockDim.x + threadIdx.x;
    int node = t >> 4;
    int lane = t & 15;
    if (node >= N) return;
    int b = batch[node];
    float dv = g_dinv[node];
    float4 av = ((const float4*)(g_acc2 + (size_t)node * OUT_C))[lane];
    float4 gv = ((const float4*)(g_g2   + (size_t)node * OUT_C))[lane];
    float4 bv = *(const float4*)(b2 + lane * 4);
    float* gs = g_gsum + b * OUT_C + lane * 4;
    atomicAdd(gs + 0, dv * (av.x + gv.x) + bv.x);
    atomicAdd(gs + 1, dv * (av.y + gv.y) + bv.y);
    atomicAdd(gs + 2, dv * (av.z + gv.z) + bv.z);
    atomicAdd(gs + 3, dv * (av.w + gv.w) + bv.w);
    if (lane == 0) atomicAdd(&g_gcnt[b], 1.0f);
}

__global__ void divide_kernel(float* __restrict__ out, int G) {
    int i = blockIdx.x * blockDim.x + threadIdx.x;
    if (i < G * OUT_C) {
        float c = g_gcnt[i / OUT_C];
        out[i] = g_gsum[i] / fmaxf(c, 1.0f);
    }
}

// ---------------- launch ----------------
extern "C" void kernel_launch(void* const* d_in, const int* in_sizes, int n_in,
                              void* d_out, int out_size) {
    const float* x   = (const float*)d_in[0];
    const float* W1  = (const float*)d_in[1];
    const float* b1  = (const float*)d_in[2];
    const float* W2  = (const float*)d_in[3];
    const float* b2  = (const float*)d_in[4];
    const int*   ei  = (const int*)d_in[5];   // int32 (JAX x64 disabled)
    const int*   bat = (const int*)d_in[6];

    const int N = in_sizes[0] / IN_C;      // 50000
    const int E = in_sizes[5] / 2;         // 625000
    const int G = out_size / OUT_C;        // 128

    const int* src = ei;
    const int* dst = ei + E;

    void *p_degi, *p_acc1, *p_acc2, *p_gsum, *p_gcnt;
    cudaGetSymbolAddress(&p_degi, g_degi);
    cudaGetSymbolAddress(&p_acc1, g_acc1);
    cudaGetSymbolAddress(&p_acc2, g_acc2);
    cudaGetSymbolAddress(&p_gsum, g_gsum);
    cudaGetSymbolAddress(&p_gcnt, g_gcnt);

    cudaMemsetAsync(p_degi, 0, (size_t)N * sizeof(int));
    cudaMemsetAsync(p_acc1, 0, (size_t)N * HID_C * sizeof(float));
    cudaMemsetAsync(p_acc2, 0, (size_t)N * OUT_C * sizeof(float));
    cudaMemsetAsync(p_gsum, 0, (size_t)G * OUT_C * sizeof(float));
    cudaMemsetAsync(p_gcnt, 0, (size_t)G * sizeof(float));

    deg_kernel<<<(E + 255) / 256, 256>>>(dst, E);
    dinv_kernel<<<(N + 255) / 256, 256>>>(N);

    gemm1_kernel<<<(N + 63) / 64, 256>>>(x, W1, N);
    scatter1_kernel<<<(E + 7) / 8, 256>>>(src, dst, E);   // 8 warps/block, 1 edge/warp

    gemm2_kernel<<<(N + 63) / 64, 256>>>(W2, b1, N);
    scatter2_kernel<<<(E + 15) / 16, 256>>>(src, dst, E); // 16 edges/block

    pool_kernel<<<(N + 15) / 16, 256>>>(bat, b2, N);
    divide_kernel<<<(G * OUT_C + 255) / 256, 256>>>((float*)d_out, G);
}

// round 3
// speedup vs baseline: 1.6243x; 1.6243x over previous
#include <cuda_runtime.h>
#include <cuda_bf16.h>
#include <cstddef>

// Problem constants (fixed shapes for this dataset)
#define N_NODES   50000
#define N_GRAPHS  128
#define IN_C      128
#define HID_C     128
#define OUT_C     64

// ---------------- device scratch (no allocations allowed) ----------------
__device__ int   g_degi[N_NODES];
__device__ float g_dinv[N_NODES];
__device__ float g_g1  [(size_t)N_NODES * HID_C];   // dinv * (x @ W1)
__device__ float g_acc1[(size_t)N_NODES * HID_C];   // scatter accumulator layer 1
__device__ float g_g2  [(size_t)N_NODES * OUT_C];   // dinv * (t @ W2)
__device__ float g_acc2[(size_t)N_NODES * OUT_C];   // scatter accumulator layer 2
__device__ float g_gsum[N_GRAPHS * OUT_C];
__device__ float g_gcnt[N_GRAPHS];

// vectorized global reduction: one lane-op commits 16B (sm_90+)
__device__ __forceinline__ void red_add_v4(float* p, float4 v) {
    asm volatile("red.global.add.v4.f32 [%0], {%1, %2, %3, %4};"
                 :: "l"(p), "f"(v.x), "f"(v.y), "f"(v.z), "f"(v.w)
                 : "memory");
}

// ---------------- degree / dinv ----------------
__global__ void deg_kernel(const int* __restrict__ dst, int E) {
    int e = blockIdx.x * blockDim.x + threadIdx.x;
    if (e < E) atomicAdd(&g_degi[dst[e]], 1);
}

__global__ void dinv_kernel(int N) {
    int i = blockIdx.x * blockDim.x + threadIdx.x;
    if (i < N) g_dinv[i] = rsqrtf((float)(1 + g_degi[i]));  // +1 self-loop
}

// ---------------- GEMM1: g1 = dinv ⊙ (X @ W1)  [M,128]x[128,128] ----------------
// BM=64, BN=128, BK=16, TM=4, TN=8, 256 threads.
__global__ void gemm1_kernel(const float* __restrict__ X,
                             const float* __restrict__ W,
                             int M) {
    __shared__ __align__(16) float xs[16][68];    // [k][m], padded
    __shared__ __align__(16) float ws[16][128];   // [k][n]

    const int tid = threadIdx.x;
    const int tn  = tid & 15;   // n-block: tn*8
    const int tm  = tid >> 4;   // m-block: tm*4
    const int row0 = blockIdx.x * 64;

    float acc[4][8];
#pragma unroll
    for (int m = 0; m < 4; m++)
#pragma unroll
        for (int n = 0; n < 8; n++) acc[m][n] = 0.f;

    const int lm = tid >> 2;          // 0..63 (row within tile for loads)
    const int lk = (tid & 3) * 4;     // k-quad for loads

    for (int k0 = 0; k0 < IN_C; k0 += 16) {
        // load X tile (transposed into xs)
        {
            int row = row0 + lm;
            float4 v = make_float4(0.f, 0.f, 0.f, 0.f);
            if (row < M)
                v = *(const float4*)(X + (size_t)row * IN_C + k0 + lk);
            xs[lk + 0][lm] = v.x;
            xs[lk + 1][lm] = v.y;
            xs[lk + 2][lm] = v.z;
            xs[lk + 3][lm] = v.w;
        }
        // load W tile: 16x128 = 512 float4, 2 per thread
#pragma unroll
        for (int i = 0; i < 2; i++) {
            int idx4 = tid + i * 256;      // 0..511
            int k  = idx4 >> 5;            // /32 float4 per row
            int n4 = idx4 & 31;
            *(float4*)(&ws[k][n4 * 4]) =
                *(const float4*)(W + (size_t)(k0 + k) * HID_C + n4 * 4);
        }
        __syncthreads();

#pragma unroll
        for (int k = 0; k < 16; k++) {
            float xr[4], wr[8];
#pragma unroll
            for (int m = 0; m < 4; m++) xr[m] = xs[k][tm * 4 + m];
#pragma unroll
            for (int n = 0; n < 8; n++) wr[n] = ws[k][tn * 8 + n];
#pragma unroll
            for (int m = 0; m < 4; m++)
#pragma unroll
                for (int n = 0; n < 8; n++) acc[m][n] += xr[m] * wr[n];
        }
        __syncthreads();
    }

#pragma unroll
    for (int m = 0; m < 4; m++) {
        int row = row0 + tm * 4 + m;
        if (row < M) {
            float d = g_dinv[row];
            float* out = g_g1 + (size_t)row * HID_C + tn * 8;
#pragma unroll
            for (int n = 0; n < 8; n++) out[n] = d * acc[m][n];
        }
    }
}

// ---------------- scatter layer 1: acc1[dst] += g1[src] (128 floats/edge) ----------------
// one warp per edge, one red.v4 per lane (32 x 16B = 512B)
__global__ void scatter1_kernel(const int* __restrict__ src,
                                const int* __restrict__ dst,
                                int E) {
    int warp = (blockIdx.x * blockDim.x + threadIdx.x) >> 5;
    int lane = threadIdx.x & 31;
    if (warp >= E) return;
    int s = src[warp];
    int d = dst[warp];
    float4 v = ((const float4*)(g_g1 + (size_t)s * HID_C))[lane];
    red_add_v4(g_acc1 + (size_t)d * HID_C + lane * 4, v);
}

// ---------------- GEMM2 (fused): t = relu(dinv*(acc1+g1)+b1); g2 = dinv ⊙ (t @ W2) ----------------
// BM=64, BN=64, BK=16, TM=4, TN=4, 256 threads.
__global__ void gemm2_kernel(const float* __restrict__ W2,
                             const float* __restrict__ b1,
                             int M) {
    __shared__ __align__(16) float xs[16][68];   // [k][m]
    __shared__ __align__(16) float ws[16][64];   // [k][n]

    const int tid = threadIdx.x;
    const int tn  = tid & 15;   // n-block: tn*4
    const int tm  = tid >> 4;   // m-block: tm*4
    const int row0 = blockIdx.x * 64;

    float acc[4][4];
#pragma unroll
    for (int m = 0; m < 4; m++)
#pragma unroll
        for (int n = 0; n < 4; n++) acc[m][n] = 0.f;

    const int lm = tid >> 2;
    const int lk = (tid & 3) * 4;

    for (int k0 = 0; k0 < HID_C; k0 += 16) {
        // build input tile on the fly: relu(dinv*(acc1+g1)+b1)
        {
            int row = row0 + lm;
            float4 r = make_float4(0.f, 0.f, 0.f, 0.f);
            if (row < M) {
                float dv = g_dinv[row];
                float4 av = *(const float4*)(g_acc1 + (size_t)row * HID_C + k0 + lk);
                float4 gv = *(const float4*)(g_g1   + (size_t)row * HID_C + k0 + lk);
                float4 bv = *(const float4*)(b1 + k0 + lk);
                r.x = fmaxf(dv * (av.x + gv.x) + bv.x, 0.f);
                r.y = fmaxf(dv * (av.y + gv.y) + bv.y, 0.f);
                r.z = fmaxf(dv * (av.z + gv.z) + bv.z, 0.f);
                r.w = fmaxf(dv * (av.w + gv.w) + bv.w, 0.f);
            }
            xs[lk + 0][lm] = r.x;
            xs[lk + 1][lm] = r.y;
            xs[lk + 2][lm] = r.z;
            xs[lk + 3][lm] = r.w;
        }
        // load W2 tile: 16x64 = 256 float4, 1 per thread
        {
            int k  = tid >> 4;
            int n4 = tid & 15;
            *(float4*)(&ws[k][n4 * 4]) =
                *(const float4*)(W2 + (size_t)(k0 + k) * OUT_C + n4 * 4);
        }
        __syncthreads();

#pragma unroll
        for (int k = 0; k < 16; k++) {
            float xr[4], wr[4];
#pragma unroll
            for (int m = 0; m < 4; m++) xr[m] = xs[k][tm * 4 + m];
#pragma unroll
            for (int n = 0; n < 4; n++) wr[n] = ws[k][tn * 4 + n];
#pragma unroll
            for (int m = 0; m < 4; m++)
#pragma unroll
                for (int n = 0; n < 4; n++) acc[m][n] += xr[m] * wr[n];
        }
        __syncthreads();
    }

#pragma unroll
    for (int m = 0; m < 4; m++) {
        int row = row0 + tm * 4 + m;
        if (row < M) {
            float d = g_dinv[row];
            float* out = g_g2 + (size_t)row * OUT_C + tn * 4;
#pragma unroll
            for (int n = 0; n < 4; n++) out[n] = d * acc[m][n];
        }
    }
}

// ---------------- scatter layer 2: acc2[dst] += g2[src] (64 floats/edge, 16 lanes/edge) ----------------
__global__ void scatter2_kernel(const int* __restrict__ src,
                                const int* __restrict__ dst,
                                int E) {
    int t = blockIdx.x * blockDim.x + threadIdx.x;
    int e = t >> 4;
    int lane = t & 15;
    if (e >= E) return;
    int s = src[e];
    int d = dst[e];
    float4 v = ((const float4*)(g_g2 + (size_t)s * OUT_C))[lane];
    red_add_v4(g_acc2 + (size_t)d * OUT_C + lane * 4, v);
}

// ---------------- pool: out2 = dinv*(acc2+g2)+b2; scatter to graph sums ----------------
__global__ void pool_kernel(const int* __restrict__ batch,
                            const float* __restrict__ b2,
                            int N) {
    int t = blockIdx.x * blockDim.x + threadIdx.x;
    int node = t >> 4;
    int lane = t & 15;
    if (node >= N) return;
    int b = batch[node];
    float dv = g_dinv[node];
    float4 av = ((const float4*)(g_acc2 + (size_t)node * OUT_C))[lane];
    float4 gv = ((const float4*)(g_g2   + (size_t)node * OUT_C))[lane];
    float4 bv = *(const float4*)(b2 + lane * 4);
    float4 r;
    r.x = dv * (av.x + gv.x) + bv.x;
    r.y = dv * (av.y + gv.y) + bv.y;
    r.z = dv * (av.z + gv.z) + bv.z;
    r.w = dv * (av.w + gv.w) + bv.w;
    red_add_v4(g_gsum + b * OUT_C + lane * 4, r);
    if (lane == 0) atomicAdd(&g_gcnt[b], 1.0f);
}

__global__ void divide_kernel(float* __restrict__ out, int G) {
    int i = blockIdx.x * blockDim.x + threadIdx.x;
    if (i < G * OUT_C) {
        float c = g_gcnt[i / OUT_C];
        out[i] = g_gsum[i] / fmaxf(c, 1.0f);
    }
}

// ---------------- launch ----------------
extern "C" void kernel_launch(void* const* d_in, const int* in_sizes, int n_in,
                              void* d_out, int out_size) {
    const float* x   = (const float*)d_in[0];
    const float* W1  = (const float*)d_in[1];
    const float* b1  = (const float*)d_in[2];
    const float* W2  = (const float*)d_in[3];
    const float* b2  = (const float*)d_in[4];
    const int*   ei  = (const int*)d_in[5];   // int32 (JAX x64 disabled)
    const int*   bat = (const int*)d_in[6];

    const int N = in_sizes[0] / IN_C;      // 50000
    const int E = in_sizes[5] / 2;         // 625000
    const int G = out_size / OUT_C;        // 128

    const int* src = ei;
    const int* dst = ei + E;

    void *p_degi, *p_acc1, *p_acc2, *p_gsum, *p_gcnt;
    cudaGetSymbolAddress(&p_degi, g_degi);
    cudaGetSymbolAddress(&p_acc1, g_acc1);
    cudaGetSymbolAddress(&p_acc2, g_acc2);
    cudaGetSymbolAddress(&p_gsum, g_gsum);
    cudaGetSymbolAddress(&p_gcnt, g_gcnt);

    cudaMemsetAsync(p_degi, 0, (size_t)N * sizeof(int));
    cudaMemsetAsync(p_acc1, 0, (size_t)N * HID_C * sizeof(float));
    cudaMemsetAsync(p_acc2, 0, (size_t)N * OUT_C * sizeof(float));
    cudaMemsetAsync(p_gsum, 0, (size_t)G * OUT_C * sizeof(float));
    cudaMemsetAsync(p_gcnt, 0, (size_t)G * sizeof(float));

    deg_kernel<<<(E + 255) / 256, 256>>>(dst, E);
    dinv_kernel<<<(N + 255) / 256, 256>>>(N);

    gemm1_kernel<<<(N + 63) / 64, 256>>>(x, W1, N);
    scatter1_kernel<<<(E + 7) / 8, 256>>>(src, dst, E);   // 8 warps/block, 1 edge/warp

    gemm2_kernel<<<(N + 63) / 64, 256>>>(W2, b1, N);
    scatter2_kernel<<<(E + 15) / 16, 256>>>(src, dst, E); // 16 edges/block

    pool_kernel<<<(N + 15) / 16, 256>>>(bat, b2, N);
    divide_kernel<<<(G * OUT_C + 255) / 256, 256>>>((float*)d_out, G);
}